// round 16
// baseline (speedup 1.0000x reference)
#include <cuda_runtime.h>
#include <cuda_bf16.h>
#include <math.h>
#include <stdint.h>

// ---------------- problem constants ----------------
#define T_TOK   2048
#define H_DIM   2048
#define LATD    1024
#define INTERD  1024
#define NE      32
#define NG      4
#define GSZ     (NE / NG)
#define TOPK    8
#define SH_INTER 4096
#define NROWS   (T_TOK * TOPK)
#define MPAD    20480            // 160 tiles * 128 rows
#define GTILES  160
#define RSCALE  2.5f
#define NCAT    5120             // LATD + SH_INTER
#define GT      4                // tokens per gate block

// ---------------- device scratch (static) ----------------
__device__ __align__(1024) __nv_bfloat16 gx_hi[T_TOK * H_DIM],      gx_lo[T_TOK * H_DIM];
__device__ __align__(1024) __nv_bfloat16 gB1_hi[NCAT * H_DIM],      gB1_lo[NCAT * H_DIM];   // [fc1; sup]
__device__ __align__(1024) __nv_bfloat16 gw1_hi[NE * INTERD * LATD], gw1_lo[NE * INTERD * LATD];
__device__ __align__(1024) __nv_bfloat16 gw2_hi[NE * LATD * INTERD], gw2_lo[NE * LATD * INTERD];
__device__ __align__(1024) __nv_bfloat16 gwcat_hi[H_DIM * NCAT],    gwcat_lo[H_DIM * NCAT]; // [fc2 | sdn]
__device__ __align__(1024) __nv_bfloat16 gxlat_hi[T_TOK * LATD],    gxlat_lo[T_TOK * LATD];
__device__ __align__(1024) __nv_bfloat16 gh_hi[MPAD * INTERD],      gh_lo[MPAD * INTERD];
__device__ __align__(1024) float         gyg[MPAD * LATD];
__device__ __align__(1024) __nv_bfloat16 gcat_hi[T_TOK * NCAT],     gcat_lo[T_TOK * NCAT];  // [ylat | s1]

__device__ int   g_topi[NROWS];
__device__ float g_wsel[NROWS];
__device__ int   g_counts[NE];
__device__ int   g_off[NE];
__device__ int   g_cursor[NE];
__device__ int   g_gtok[MPAD];      // zero-init; pads stay 0
__device__ float g_gw[MPAD];        // zero-init; pads stay 0
__device__ int   g_rowidx[NROWS];
__device__ int   g_tile_e[GTILES];
__device__ int   g_tile_m0[GTILES];
__device__ int   g_ntiles;

// ---------------- PTX helpers ----------------
__device__ __forceinline__ uint32_t smem_u32(const void* p) {
    uint32_t a;
    asm("{ .reg .u64 t; cvta.to.shared.u64 t, %1; cvt.u32.u64 %0, t; }" : "=r"(a) : "l"(p));
    return a;
}
__device__ __forceinline__ void cp16(uint32_t dst, const void* src) {
    asm volatile("cp.async.cg.shared.global [%0], [%1], 16;" :: "r"(dst), "l"(src) : "memory");
}
__device__ __forceinline__ void ldsm4(uint32_t* r, uint32_t addr) {
    asm volatile("ldmatrix.sync.aligned.m8n8.x4.shared.b16 {%0,%1,%2,%3}, [%4];"
        : "=r"(r[0]), "=r"(r[1]), "=r"(r[2]), "=r"(r[3]) : "r"(addr));
}
__device__ __forceinline__ void mma16816(float* d, const uint32_t* a, uint32_t b0, uint32_t b1) {
    asm volatile("mma.sync.aligned.m16n8k16.row.col.f32.bf16.bf16.f32 "
        "{%0,%1,%2,%3}, {%4,%5,%6,%7}, {%8,%9}, {%0,%1,%2,%3};"
        : "+f"(d[0]), "+f"(d[1]), "+f"(d[2]), "+f"(d[3])
        : "r"(a[0]), "r"(a[1]), "r"(a[2]), "r"(a[3]), "r"(b0), "r"(b1));
}
__device__ __forceinline__ void redadd(float* p, float v) {
    asm volatile("red.global.add.f32 [%0], %1;" :: "l"(p), "f"(v) : "memory");
}

// ---------------- fp32 -> bf16 hi/lo split ----------------
__device__ __forceinline__ void split_val(float v, __nv_bfloat16& h, __nv_bfloat16& l) {
    h = __float2bfloat16(v);
    l = __float2bfloat16(v - __bfloat162float(h));
}

__device__ __forceinline__ void split_store4(const float4 v, __nv_bfloat16* hi,
                                             __nv_bfloat16* lo, long elem)
{
    __nv_bfloat16 h0, h1, h2, h3, l0, l1, l2, l3;
    split_val(v.x, h0, l0); split_val(v.y, h1, l1);
    split_val(v.z, h2, l2); split_val(v.w, h3, l3);
    __nv_bfloat162* hi2 = reinterpret_cast<__nv_bfloat162*>(hi + elem);
    __nv_bfloat162* lo2 = reinterpret_cast<__nv_bfloat162*>(lo + elem);
    hi2[0] = __nv_bfloat162(h0, h1);
    hi2[1] = __nv_bfloat162(h2, h3);
    lo2[0] = __nv_bfloat162(l0, l1);
    lo2[1] = __nv_bfloat162(l2, l3);
}

// ---------------- zero out + counts (s1 head; one launch) ----------------
__global__ void zero_out_counts_kernel(float4* __restrict__ out)
{
    if (blockIdx.x == 0 && threadIdx.x < NE) g_counts[threadIdx.x] = 0;
    out[blockIdx.x * 256 + threadIdx.x] = make_float4(0.f, 0.f, 0.f, 0.f);
}

// ---------------- phase-A split: x, fc1, sup (needed by 3a/3b) ----------------
#define A0 1048576L                  // x
#define A1 (A0 + 524288L)            // fc1 -> B1[0]
#define A2 (A1 + 2097152L)           // sup -> B1[LATD*H_DIM]
#define SPLITA_BLOCKS ((A2 / 2) / 256)   // 7168

__global__ void split_a_kernel(const float4* __restrict__ x,
                               const float4* __restrict__ fc1,
                               const float4* __restrict__ sup)
{
    const long base = ((long)blockIdx.x * 256 + threadIdx.x) * 2;
    #pragma unroll
    for (int u = 0; u < 2; u++) {
        const long i = base + u;
        const float4* src; long si;
        __nv_bfloat16 *hi, *lo; long elem;
        if (i < A0)      { src = x;   si = i;      hi = gx_hi;  lo = gx_lo;  elem = si * 4; }
        else if (i < A1) { src = fc1; si = i - A0; hi = gB1_hi; lo = gB1_lo; elem = si * 4; }
        else             { src = sup; si = i - A1; hi = gB1_hi; lo = gB1_lo; elem = (long)LATD * H_DIM + si * 4; }
        split_store4(src[si], hi, lo, elem);
    }
}

// ---------------- phase-B split: w1, w2, fc2, sdn ----------------
#define B0 8388608L                  // w1
#define B1B (B0 + 8388608L)          // w2
#define B2 (B1B + 524288L)           // fc2 -> wcat pitched (row len 256 f4)
#define B3 (B2 + 2097152L)           // sdn -> wcat pitched (row len 1024 f4)
#define SPLITB_BLOCKS ((B3 / 2) / 256)   // 37888

__global__ void split_b_kernel(const float4* __restrict__ w1,
                               const float4* __restrict__ w2,
                               const float4* __restrict__ fc2,
                               const float4* __restrict__ sdn)
{
    const long base = ((long)blockIdx.x * 256 + threadIdx.x) * 2;
    #pragma unroll
    for (int u = 0; u < 2; u++) {
        const long i = base + u;
        const float4* src; long si;
        __nv_bfloat16 *hi, *lo; long elem;
        if (i < B0)       { src = w1;  si = i;       hi = gw1_hi; lo = gw1_lo; elem = si * 4; }
        else if (i < B1B) { src = w2;  si = i - B0;  hi = gw2_hi; lo = gw2_lo; elem = si * 4; }
        else if (i < B2)  { src = fc2; si = i - B1B; long row = si >> 8,  c4 = si & 255;
                            hi = gwcat_hi; lo = gwcat_lo; elem = row * NCAT + c4 * 4; }
        else              { src = sdn; si = i - B2;  long row = si >> 10, c4 = si & 1023;
                            hi = gwcat_hi; lo = gwcat_lo; elem = row * NCAT + LATD + c4 * 4; }
        split_store4(src[si], hi, lo, elem);
    }
}

// ---------------- gate + routing: 4 tokens/block (512 blocks), math identical ----------------
__global__ void gate_kernel(const float* __restrict__ x,
                            const float* __restrict__ gw,
                            const float* __restrict__ gb)
{
    __shared__ float logits[GT][NE];
    const int warp = threadIdx.x >> 5, lane = threadIdx.x & 31;
    const int t0 = blockIdx.x * GT;

    for (int task = warp; task < GT * NE; task += 8) {
        const int tt = task >> 5;
        const int e  = task & 31;
        const float* xt = x + (long)(t0 + tt) * H_DIM;
        const float* w  = gw + (long)e * H_DIM;
        float s = 0.f;
        for (int h = lane; h < H_DIM; h += 32) s = fmaf(xt[h], w[h], s);
        #pragma unroll
        for (int o = 16; o > 0; o >>= 1) s += __shfl_down_sync(0xffffffffu, s, o);
        if (lane == 0) logits[tt][e] = s;
    }
    __syncthreads();

    if (threadIdx.x < GT) {
        const int t = t0 + threadIdx.x;
        float sc[NE], sb[NE];
        #pragma unroll
        for (int e = 0; e < NE; e++) {
            float s = 1.f / (1.f + expf(-logits[threadIdx.x][e]));
            sc[e] = s; sb[e] = s + gb[e];
        }
        float gsc[NG];
        #pragma unroll
        for (int g = 0; g < NG; g++) {
            float m1 = -1e30f, m2 = -1e30f;
            #pragma unroll
            for (int j = 0; j < GSZ; j++) {
                float v = sb[g * GSZ + j];
                if (v > m1) { m2 = m1; m1 = v; } else if (v > m2) m2 = v;
            }
            gsc[g] = m1 + m2;
        }
        int g1 = 0; float b1 = gsc[0];
        for (int g = 1; g < NG; g++) if (gsc[g] > b1) { b1 = gsc[g]; g1 = g; }
        int g2 = -1; float b2 = -1e30f;
        for (int g = 0; g < NG; g++) if (g != g1 && gsc[g] > b2) { b2 = gsc[g]; g2 = g; }
        bool used[NE];
        #pragma unroll
        for (int e = 0; e < NE; e++) used[e] = !((e / GSZ) == g1 || (e / GSZ) == g2);
        float wtmp[TOPK]; float wsum = 0.f;
        #pragma unroll
        for (int k = 0; k < TOPK; k++) {
            int best = -1; float bv = -1e30f;
            for (int e = 0; e < NE; e++)
                if (!used[e] && sb[e] > bv) { bv = sb[e]; best = e; }
            used[best] = true;
            g_topi[t * TOPK + k] = best;
            atomicAdd(&g_counts[best], 1);
            wtmp[k] = sc[best]; wsum += sc[best];
        }
        float inv = RSCALE / wsum;
        #pragma unroll
        for (int k = 0; k < TOPK; k++) g_wsel[t * TOPK + k] = wtmp[k] * inv;
    }
}

__global__ void scan_kernel()
{
    if (threadIdx.x == 0) {
        int s = 0, nt = 0;
        for (int e = 0; e < NE; e++) {
            g_off[e] = s; g_cursor[e] = s;
            int c = g_counts[e];
            int tiles = (c + 127) >> 7;
            for (int j = 0; j < tiles; j++) { g_tile_e[nt] = e; g_tile_m0[nt] = s + j * 128; nt++; }
            s += tiles << 7;
        }
        g_ntiles = nt;
    }
}

__global__ void scatter_kernel()
{
    int i = blockIdx.x * blockDim.x + threadIdx.x;
    if (i < NROWS) {
        int e = g_topi[i];
        int pos = atomicAdd(&g_cursor[e], 1);
        g_gtok[pos] = i / TOPK;
        g_gw[pos]   = g_wsel[i];
        g_rowidx[i] = pos;
    }
}

// combine: ylat[t] = sum_k yg[rowidx[t,k]]; split into gcat cols 0-1023 (pitch NCAT)
__global__ void combine_kernel()
{
    int t = blockIdx.x;
    int l4 = threadIdx.x;
    int ridx[TOPK];
    #pragma unroll
    for (int k = 0; k < TOPK; k++) ridx[k] = g_rowidx[t * TOPK + k];
    float4 s = make_float4(0.f, 0.f, 0.f, 0.f);
    #pragma unroll
    for (int k = 0; k < TOPK; k++) {
        const float4 v = reinterpret_cast<const float4*>(gyg + (long)ridx[k] * LATD)[l4];
        s.x += v.x; s.y += v.y; s.z += v.z; s.w += v.w;
    }
    split_store4(s, gcat_hi, gcat_lo, (long)t * NCAT + l4 * 4);
}

// ---------------- HMMA GEMM-NT, 3-term bf16 split ----------------
// EPI: 0 fp32 store; 2 relu2*rscale -> split; 5 mixed; 6 red.global.add.f32
#define STAGE_BYTES 32768
#define GEMM_SMEM (3 * STAGE_BYTES)

template<int EPI, bool GROUPED, bool GATHER>
__global__ void __launch_bounds__(256, 2)
hgemm(const __nv_bfloat16* __restrict__ Ah_, const __nv_bfloat16* __restrict__ Al_,
      const __nv_bfloat16* __restrict__ Bh_, const __nv_bfloat16* __restrict__ Bl_,
      float* __restrict__ Cf,
      __nv_bfloat16* __restrict__ C1hi, __nv_bfloat16* __restrict__ C1lo,
      __nv_bfloat16* __restrict__ C2hi, __nv_bfloat16* __restrict__ C2lo,
      const float* __restrict__ rsc,
      int N, int K, int ldA, int ldB, int expertN, int col_off)
{
    extern __shared__ char smem[];
    int m0, brow0;
    if (GROUPED) {
        if ((int)blockIdx.y >= g_ntiles) return;
        m0    = g_tile_m0[blockIdx.y];
        brow0 = g_tile_e[blockIdx.y] * expertN + blockIdx.x * 128;
    } else {
        m0    = blockIdx.y * 128;
        brow0 = blockIdx.x * 128;
    }
    const int col0 = blockIdx.x * 128 + col_off;
    const int tid = threadIdx.x;
    const int wid = tid >> 5, lane = tid & 31;
    const uint32_t sb = smem_u32(smem);

    const int lrow = tid >> 2;
    const int lch  = tid & 3;
    const uint32_t so0 = (uint32_t)(lrow * 64 + ((lch ^ (lrow & 3)) << 4));
    const uint32_t so1 = so0 + 64 * 64;

    long ra0, ra1;
    if (GATHER) {
        ra0 = (long)g_gtok[m0 + lrow] * ldA;
        ra1 = (long)g_gtok[m0 + lrow + 64] * ldA;
    } else {
        ra0 = (long)(m0 + lrow) * ldA;
        ra1 = (long)(m0 + lrow + 64) * ldA;
    }
    const __nv_bfloat16* rowAh0 = Ah_ + ra0;
    const __nv_bfloat16* rowAh1 = Ah_ + ra1;
    const __nv_bfloat16* rowAl0 = Al_ + ra0;
    const __nv_bfloat16* rowAl1 = Al_ + ra1;
    const __nv_bfloat16* rowBh0 = Bh_ + (long)(brow0 + lrow) * ldB;
    const __nv_bfloat16* rowBh1 = rowBh0 + (long)64 * ldB;
    const __nv_bfloat16* rowBl0 = Bl_ + (long)(brow0 + lrow) * ldB;
    const __nv_bfloat16* rowBl1 = rowBl0 + (long)64 * ldB;

    const int wm = (wid & 3) * 32, wn = (wid >> 2) * 64;
    const int arow = wm + (lane & 15);
    const int brow = wn + (lane & 15);
    const int lhalf = lane >> 4;

    float acc[2][8][4];
    #pragma unroll
    for (int mi = 0; mi < 2; mi++)
        #pragma unroll
        for (int ni = 0; ni < 8; ni++)
            #pragma unroll
            for (int r = 0; r < 4; r++) acc[mi][ni][r] = 0.f;

    const int NT = K >> 5;

#define LOAD_STAGE(kt, s) do {                                                  \
    const long ko = (long)(kt) * 32 + lch * 8;                                  \
    uint32_t base = sb + (uint32_t)(s) * STAGE_BYTES;                           \
    cp16(base         + so0, rowAh0 + ko);                                      \
    cp16(base         + so1, rowAh1 + ko);                                      \
    cp16(base + 8192  + so0, rowAl0 + ko);                                      \
    cp16(base + 8192  + so1, rowAl1 + ko);                                      \
    cp16(base + 16384 + so0, rowBh0 + ko);                                      \
    cp16(base + 16384 + so1, rowBh1 + ko);                                      \
    cp16(base + 24576 + so0, rowBl0 + ko);                                      \
    cp16(base + 24576 + so1, rowBl1 + ko);                                      \
    asm volatile("cp.async.commit_group;" ::: "memory");                        \
} while (0)

    LOAD_STAGE(0, 0);
    LOAD_STAGE(1, 1);

    for (int kt = 0; kt < NT; kt++) {
        if (kt + 1 < NT) {
            asm volatile("cp.async.wait_group 1;" ::: "memory");
        } else {
            asm volatile("cp.async.wait_group 0;" ::: "memory");
        }
        __syncthreads();
        if (kt + 2 < NT) {
            LOAD_STAGE(kt + 2, (kt + 2) % 3);
        }

        const uint32_t sA = sb + (uint32_t)(kt % 3) * STAGE_BYTES;
        #pragma unroll
        for (int ks = 0; ks < 2; ks++) {
            const uint32_t axor = (uint32_t)((((ks * 2 + lhalf) ^ (arow & 3))) << 4);
            const uint32_t bxor = (uint32_t)((((ks * 2 + lhalf) ^ (brow & 3))) << 4);
            uint32_t ah[2][4], al[2][4];
            ldsm4(ah[0], sA + (uint32_t)(arow * 64) + axor);
            ldsm4(ah[1], sA + (uint32_t)((arow + 16) * 64) + axor);
            ldsm4(al[0], sA + 8192 + (uint32_t)(arow * 64) + axor);
            ldsm4(al[1], sA + 8192 + (uint32_t)((arow + 16) * 64) + axor);
            #pragma unroll
            for (int ng = 0; ng < 4; ng++) {
                uint32_t bh[4], bl[4];
                const uint32_t bo = (uint32_t)((brow + ng * 16) * 64);
                ldsm4(bh, sA + 16384 + bo + bxor);
                ldsm4(bl, sA + 24576 + bo + bxor);
                #pragma unroll
                for (int mi = 0; mi < 2; mi++) {
                    mma16816(acc[mi][ng * 2],     ah[mi], bh[0], bh[2]);
                    mma16816(acc[mi][ng * 2 + 1], ah[mi], bh[1], bh[3]);
                    mma16816(acc[mi][ng * 2],     ah[mi], bl[0], bl[2]);
                    mma16816(acc[mi][ng * 2 + 1], ah[mi], bl[1], bl[3]);
                    mma16816(acc[mi][ng * 2],     al[mi], bh[0], bh[2]);
                    mma16816(acc[mi][ng * 2 + 1], al[mi], bh[1], bh[3]);
                }
            }
        }
    }
#undef LOAD_STAGE

    const bool lowCols = (col0 < LATD);   // for EPI 5
    #pragma unroll
    for (int mi = 0; mi < 2; mi++) {
        #pragma unroll
        for (int ni = 0; ni < 8; ni++) {
            const float* d = acc[mi][ni];
            const int rr = m0 + wm + mi * 16 + (lane >> 2);
            const int cc = col0 + wn + ni * 8 + (lane & 3) * 2;
            #pragma unroll
            for (int half = 0; half < 2; half++) {
                const int r = rr + half * 8;
                float v0 = d[half * 2], v1 = d[half * 2 + 1];
                if (EPI == 0) {
                    *reinterpret_cast<float2*>(&Cf[(long)r * N + cc]) = make_float2(v0, v1);
                } else if (EPI == 6) {
                    redadd(&Cf[(long)r * N + cc], v0);
                    redadd(&Cf[(long)r * N + cc + 1], v1);
                } else if (EPI == 2) {
                    const float w = rsc[r];
                    float u0 = fmaxf(v0, 0.f); v0 = u0 * u0 * w;
                    float u1 = fmaxf(v1, 0.f); v1 = u1 * u1 * w;
                    __nv_bfloat16 h0, l0, h1, l1;
                    split_val(v0, h0, l0); split_val(v1, h1, l1);
                    *reinterpret_cast<__nv_bfloat162*>(&C1hi[(long)r * N + cc]) = __nv_bfloat162(h0, h1);
                    *reinterpret_cast<__nv_bfloat162*>(&C1lo[(long)r * N + cc]) = __nv_bfloat162(l0, l1);
                } else { // EPI == 5
                    if (lowCols) {
                        __nv_bfloat16 h0, l0, h1, l1;
                        split_val(v0, h0, l0); split_val(v1, h1, l1);
                        *reinterpret_cast<__nv_bfloat162*>(&C1hi[(long)r * LATD + cc]) = __nv_bfloat162(h0, h1);
                        *reinterpret_cast<__nv_bfloat162*>(&C1lo[(long)r * LATD + cc]) = __nv_bfloat162(l0, l1);
                    } else {
                        float u0 = fmaxf(v0, 0.f); v0 = u0 * u0;
                        float u1 = fmaxf(v1, 0.f); v1 = u1 * u1;
                        __nv_bfloat16 h0, l0, h1, l1;
                        split_val(v0, h0, l0); split_val(v1, h1, l1);
                        *reinterpret_cast<__nv_bfloat162*>(&C2hi[(long)r * NCAT + cc]) = __nv_bfloat162(h0, h1);
                        *reinterpret_cast<__nv_bfloat162*>(&C2lo[(long)r * NCAT + cc]) = __nv_bfloat162(l0, l1);
                    }
                }
            }
        }
    }
}

// ---------------- host ----------------
static void* sym(const void* s) { void* p; cudaGetSymbolAddress(&p, s); return p; }

extern "C" void kernel_launch(void* const* d_in, const int* in_sizes, int n_in,
                              void* d_out, int out_size)
{
    const float* x      = (const float*)d_in[0];
    const float* gate_w = (const float*)d_in[1];
    const float* gate_b = (const float*)d_in[2];
    const float* fc1_w  = (const float*)d_in[3];
    const float* fc2_w  = (const float*)d_in[4];
    const float* w1     = (const float*)d_in[5];
    const float* w2     = (const float*)d_in[6];
    const float* sup    = (const float*)d_in[7];
    const float* sdn    = (const float*)d_in[8];
    float* out = (float*)d_out;

    __nv_bfloat16* px_hi   = (__nv_bfloat16*)sym(gx_hi);   __nv_bfloat16* px_lo   = (__nv_bfloat16*)sym(gx_lo);
    __nv_bfloat16* pB1_hi  = (__nv_bfloat16*)sym(gB1_hi);  __nv_bfloat16* pB1_lo  = (__nv_bfloat16*)sym(gB1_lo);
    __nv_bfloat16* pw1_hi  = (__nv_bfloat16*)sym(gw1_hi);  __nv_bfloat16* pw1_lo  = (__nv_bfloat16*)sym(gw1_lo);
    __nv_bfloat16* pw2_hi  = (__nv_bfloat16*)sym(gw2_hi);  __nv_bfloat16* pw2_lo  = (__nv_bfloat16*)sym(gw2_lo);
    __nv_bfloat16* pwc_hi  = (__nv_bfloat16*)sym(gwcat_hi); __nv_bfloat16* pwc_lo = (__nv_bfloat16*)sym(gwcat_lo);
    __nv_bfloat16* pxlat_hi = (__nv_bfloat16*)sym(gxlat_hi); __nv_bfloat16* pxlat_lo = (__nv_bfloat16*)sym(gxlat_lo);
    __nv_bfloat16* ph_hi   = (__nv_bfloat16*)sym(gh_hi);   __nv_bfloat16* ph_lo   = (__nv_bfloat16*)sym(gh_lo);
    float*         pyg     = (float*)sym(gyg);
    __nv_bfloat16* pcat_hi = (__nv_bfloat16*)sym(gcat_hi); __nv_bfloat16* pcat_lo = (__nv_bfloat16*)sym(gcat_lo);
    float*         pgw     = (float*)sym(g_gw);

    cudaFuncSetAttribute((hgemm<6, false, false>), cudaFuncAttributeMaxDynamicSharedMemorySize, GEMM_SMEM);
    cudaFuncSetAttribute((hgemm<5, false, false>), cudaFuncAttributeMaxDynamicSharedMemorySize, GEMM_SMEM);
    cudaFuncSetAttribute((hgemm<2, true, true>),   cudaFuncAttributeMaxDynamicSharedMemorySize, GEMM_SMEM);
    cudaFuncSetAttribute((hgemm<0, true, false>),  cudaFuncAttributeMaxDynamicSharedMemorySize, GEMM_SMEM);

    // lazy one-time side stream + events (host objects only; no device allocation)
    static bool s_init = false;
    static cudaStream_t s1;
    static cudaEvent_t eFork, eSplitA, eSplitB, eRoute, e7a;
    if (!s_init) {
        cudaStreamCreateWithFlags(&s1, cudaStreamNonBlocking);
        cudaEventCreateWithFlags(&eFork,   cudaEventDisableTiming);
        cudaEventCreateWithFlags(&eSplitA, cudaEventDisableTiming);
        cudaEventCreateWithFlags(&eSplitB, cudaEventDisableTiming);
        cudaEventCreateWithFlags(&eRoute,  cudaEventDisableTiming);
        cudaEventCreateWithFlags(&e7a,     cudaEventDisableTiming);
        s_init = true;
    }

    // ---- fork side stream (R11/R15 structure) ----
    cudaEventRecord(eFork, 0);
    cudaStreamWaitEvent(s1, eFork, 0);

    // main: splits start immediately (zero_out moved to s1)
    split_a_kernel<<<SPLITA_BLOCKS, 256>>>((const float4*)x, (const float4*)fc1_w,
                                           (const float4*)sup);
    cudaEventRecord(eSplitA, 0);

    split_b_kernel<<<SPLITB_BLOCKS, 256>>>((const float4*)w1, (const float4*)w2,
                                           (const float4*)fc2_w, (const float4*)sdn);
    cudaEventRecord(eSplitB, 0);

    // s1: zero out+counts, routing chain, then 3b, then G7a
    zero_out_counts_kernel<<<T_TOK * H_DIM / 4 / 256, 256, 0, s1>>>((float4*)out);
    gate_kernel<<<T_TOK / GT, 256, 0, s1>>>(x, gate_w, gate_b);
    scan_kernel<<<1, 32, 0, s1>>>();
    scatter_kernel<<<(NROWS + 255) / 256, 256, 0, s1>>>();
    cudaEventRecord(eRoute, s1);
    // s1: 3b needs phase-A split only
    cudaStreamWaitEvent(s1, eSplitA, 0);
    hgemm<5, false, false><<<dim3(SH_INTER / 128, T_TOK / 128), 256, GEMM_SMEM, s1>>>(
        px_hi, px_lo, pB1_hi + (long)LATD * H_DIM, pB1_lo + (long)LATD * H_DIM, nullptr,
        nullptr, nullptr, pcat_hi, pcat_lo, nullptr,
        NCAT, H_DIM, H_DIM, H_DIM, 0, LATD);
    // s1: G7a (RED-add) needs 3b output + wcat; zero_out ordered earlier on s1
    cudaStreamWaitEvent(s1, eSplitB, 0);
    hgemm<6, false, false><<<dim3(H_DIM / 128, T_TOK / 128), 256, GEMM_SMEM, s1>>>(
        pcat_hi + LATD, pcat_lo + LATD, pwc_hi + LATD, pwc_lo + LATD, out,
        nullptr, nullptr, nullptr, nullptr, nullptr,
        H_DIM, SH_INTER, NCAT, NCAT, 0, 0);
    cudaEventRecord(e7a, s1);

    // main: 3a = x @ fc1^T -> xlat split
    hgemm<5, false, false><<<dim3(LATD / 128, T_TOK / 128), 256, GEMM_SMEM>>>(
        px_hi, px_lo, pB1_hi, pB1_lo, nullptr,
        pxlat_hi, pxlat_lo, nullptr, nullptr, nullptr,
        NCAT, H_DIM, H_DIM, H_DIM, 0, 0);

    // G4 needs routing + w1 (eRoute also orders zero_out before all main-stream RED consumers)
    cudaStreamWaitEvent(0, eRoute, 0);
    hgemm<2, true, true><<<dim3(INTERD / 128, GTILES), 256, GEMM_SMEM>>>(
        pxlat_hi, pxlat_lo, pw1_hi, pw1_lo, nullptr,
        ph_hi, ph_lo, nullptr, nullptr, pgw,
        INTERD, LATD, LATD, LATD, INTERD, 0);

    // G5: yg = h @ w2[e]^T (fp32)
    hgemm<0, true, false><<<dim3(LATD / 128, GTILES), 256, GEMM_SMEM>>>(
        ph_hi, ph_lo, pw2_hi, pw2_lo, pyg,
        nullptr, nullptr, nullptr, nullptr, nullptr,
        LATD, INTERD, INTERD, INTERD, LATD, 0);

    // combine -> gcat cols 0-1023
    combine_kernel<<<T_TOK, 256>>>();

    // G7b (RED-add): overlaps G7a's tail; order-free commutative sum
    hgemm<6, false, false><<<dim3(H_DIM / 128, T_TOK / 128), 256, GEMM_SMEM>>>(
        pcat_hi, pcat_lo, pwc_hi, pwc_lo, out,
        nullptr, nullptr, nullptr, nullptr, nullptr,
        H_DIM, LATD, NCAT, NCAT, 0, 0);

    // join s1 into origin stream for graph-capture completeness (after G7b)
    cudaStreamWaitEvent(0, e7a, 0);
}

// round 17
// speedup vs baseline: 1.0031x; 1.0031x over previous
#include <cuda_runtime.h>
#include <cuda_bf16.h>
#include <math.h>
#include <stdint.h>

// ---------------- problem constants ----------------
#define T_TOK   2048
#define H_DIM   2048
#define LATD    1024
#define INTERD  1024
#define NE      32
#define NG      4
#define GSZ     (NE / NG)
#define TOPK    8
#define SH_INTER 4096
#define NROWS   (T_TOK * TOPK)
#define MPAD    20480            // 160 tiles * 128 rows
#define GTILES  160
#define RSCALE  2.5f
#define NCAT    5120             // LATD + SH_INTER
#define GT      4                // tokens per gate block

// ---------------- device scratch (static) ----------------
__device__ __align__(1024) __nv_bfloat16 gx_hi[T_TOK * H_DIM],      gx_lo[T_TOK * H_DIM];
__device__ __align__(1024) __nv_bfloat16 gB1_hi[NCAT * H_DIM],      gB1_lo[NCAT * H_DIM];   // [fc1; sup]
__device__ __align__(1024) __nv_bfloat16 gw1_hi[NE * INTERD * LATD], gw1_lo[NE * INTERD * LATD];
__device__ __align__(1024) __nv_bfloat16 gw2_hi[NE * LATD * INTERD], gw2_lo[NE * LATD * INTERD];
__device__ __align__(1024) __nv_bfloat16 gwcat_hi[H_DIM * NCAT],    gwcat_lo[H_DIM * NCAT]; // [fc2 | sdn]
__device__ __align__(1024) __nv_bfloat16 gxlat_hi[T_TOK * LATD],    gxlat_lo[T_TOK * LATD];
__device__ __align__(1024) __nv_bfloat16 gh_hi[MPAD * INTERD],      gh_lo[MPAD * INTERD];
__device__ __align__(1024) float         gyg[MPAD * LATD];
__device__ __align__(1024) __nv_bfloat16 gcat_hi[T_TOK * NCAT],     gcat_lo[T_TOK * NCAT];  // [ylat | s1]

__device__ int   g_topi[NROWS];
__device__ float g_wsel[NROWS];
__device__ int   g_counts[NE];
__device__ int   g_off[NE];
__device__ int   g_cursor[NE];
__device__ int   g_gtok[MPAD];      // zero-init; pads stay 0
__device__ float g_gw[MPAD];        // zero-init; pads stay 0
__device__ int   g_rowidx[NROWS];
__device__ int   g_tile_e[GTILES];
__device__ int   g_tile_m0[GTILES];
__device__ int   g_ntiles;

// ---------------- PTX helpers ----------------
__device__ __forceinline__ uint32_t smem_u32(const void* p) {
    uint32_t a;
    asm("{ .reg .u64 t; cvta.to.shared.u64 t, %1; cvt.u32.u64 %0, t; }" : "=r"(a) : "l"(p));
    return a;
}
__device__ __forceinline__ void cp16(uint32_t dst, const void* src) {
    asm volatile("cp.async.cg.shared.global [%0], [%1], 16;" :: "r"(dst), "l"(src) : "memory");
}
__device__ __forceinline__ void ldsm4(uint32_t* r, uint32_t addr) {
    asm volatile("ldmatrix.sync.aligned.m8n8.x4.shared.b16 {%0,%1,%2,%3}, [%4];"
        : "=r"(r[0]), "=r"(r[1]), "=r"(r[2]), "=r"(r[3]) : "r"(addr));
}
__device__ __forceinline__ void mma16816(float* d, const uint32_t* a, uint32_t b0, uint32_t b1) {
    asm volatile("mma.sync.aligned.m16n8k16.row.col.f32.bf16.bf16.f32 "
        "{%0,%1,%2,%3}, {%4,%5,%6,%7}, {%8,%9}, {%0,%1,%2,%3};"
        : "+f"(d[0]), "+f"(d[1]), "+f"(d[2]), "+f"(d[3])
        : "r"(a[0]), "r"(a[1]), "r"(a[2]), "r"(a[3]), "r"(b0), "r"(b1));
}
__device__ __forceinline__ void redadd(float* p, float v) {
    asm volatile("red.global.add.f32 [%0], %1;" :: "l"(p), "f"(v) : "memory");
}

// ---------------- fp32 -> bf16 hi/lo split ----------------
__device__ __forceinline__ void split_val(float v, __nv_bfloat16& h, __nv_bfloat16& l) {
    h = __float2bfloat16(v);
    l = __float2bfloat16(v - __bfloat162float(h));
}

__device__ __forceinline__ void split_store4(const float4 v, __nv_bfloat16* hi,
                                             __nv_bfloat16* lo, long elem)
{
    __nv_bfloat16 h0, h1, h2, h3, l0, l1, l2, l3;
    split_val(v.x, h0, l0); split_val(v.y, h1, l1);
    split_val(v.z, h2, l2); split_val(v.w, h3, l3);
    __nv_bfloat162* hi2 = reinterpret_cast<__nv_bfloat162*>(hi + elem);
    __nv_bfloat162* lo2 = reinterpret_cast<__nv_bfloat162*>(lo + elem);
    hi2[0] = __nv_bfloat162(h0, h1);
    hi2[1] = __nv_bfloat162(h2, h3);
    lo2[0] = __nv_bfloat162(l0, l1);
    lo2[1] = __nv_bfloat162(l2, l3);
}

// ---------------- zero the output (s2; enables RED-add epilogues) ----------------
__global__ void zero_out_kernel(float4* __restrict__ out)
{
    out[blockIdx.x * 256 + threadIdx.x] = make_float4(0.f, 0.f, 0.f, 0.f);
}

// ---------------- phase-A split: x, fc1, sup (needed by 3a/3b) ----------------
#define A0 1048576L                  // x
#define A1 (A0 + 524288L)            // fc1 -> B1[0]
#define A2 (A1 + 2097152L)           // sup -> B1[LATD*H_DIM]
#define SPLITA_BLOCKS ((A2 / 2) / 256)   // 7168

__global__ void split_a_kernel(const float4* __restrict__ x,
                               const float4* __restrict__ fc1,
                               const float4* __restrict__ sup)
{
    const long base = ((long)blockIdx.x * 256 + threadIdx.x) * 2;
    #pragma unroll
    for (int u = 0; u < 2; u++) {
        const long i = base + u;
        const float4* src; long si;
        __nv_bfloat16 *hi, *lo; long elem;
        if (i < A0)      { src = x;   si = i;      hi = gx_hi;  lo = gx_lo;  elem = si * 4; }
        else if (i < A1) { src = fc1; si = i - A0; hi = gB1_hi; lo = gB1_lo; elem = si * 4; }
        else             { src = sup; si = i - A1; hi = gB1_hi; lo = gB1_lo; elem = (long)LATD * H_DIM + si * 4; }
        split_store4(src[si], hi, lo, elem);
    }
}

// ---------------- phase-B split: w1, w2, fc2, sdn ----------------
#define B0 8388608L                  // w1
#define B1B (B0 + 8388608L)          // w2
#define B2 (B1B + 524288L)           // fc2 -> wcat pitched (row len 256 f4)
#define B3 (B2 + 2097152L)           // sdn -> wcat pitched (row len 1024 f4)
#define SPLITB_BLOCKS ((B3 / 2) / 256)   // 37888

__global__ void split_b_kernel(const float4* __restrict__ w1,
                               const float4* __restrict__ w2,
                               const float4* __restrict__ fc2,
                               const float4* __restrict__ sdn)
{
    const long base = ((long)blockIdx.x * 256 + threadIdx.x) * 2;
    #pragma unroll
    for (int u = 0; u < 2; u++) {
        const long i = base + u;
        const float4* src; long si;
        __nv_bfloat16 *hi, *lo; long elem;
        if (i < B0)       { src = w1;  si = i;       hi = gw1_hi; lo = gw1_lo; elem = si * 4; }
        else if (i < B1B) { src = w2;  si = i - B0;  hi = gw2_hi; lo = gw2_lo; elem = si * 4; }
        else if (i < B2)  { src = fc2; si = i - B1B; long row = si >> 8,  c4 = si & 255;
                            hi = gwcat_hi; lo = gwcat_lo; elem = row * NCAT + c4 * 4; }
        else              { src = sdn; si = i - B2;  long row = si >> 10, c4 = si & 1023;
                            hi = gwcat_hi; lo = gwcat_lo; elem = row * NCAT + LATD + c4 * 4; }
        split_store4(src[si], hi, lo, elem);
    }
}

// ---------------- gate + routing: 4 tokens/block (512 blocks), math identical ----------------
__global__ void zero_counts_kernel() { if (threadIdx.x < NE) g_counts[threadIdx.x] = 0; }

__global__ void gate_kernel(const float* __restrict__ x,
                            const float* __restrict__ gw,
                            const float* __restrict__ gb)
{
    __shared__ float logits[GT][NE];
    const int warp = threadIdx.x >> 5, lane = threadIdx.x & 31;
    const int t0 = blockIdx.x * GT;

    for (int task = warp; task < GT * NE; task += 8) {
        const int tt = task >> 5;
        const int e  = task & 31;
        const float* xt = x + (long)(t0 + tt) * H_DIM;
        const float* w  = gw + (long)e * H_DIM;
        float s = 0.f;
        for (int h = lane; h < H_DIM; h += 32) s = fmaf(xt[h], w[h], s);
        #pragma unroll
        for (int o = 16; o > 0; o >>= 1) s += __shfl_down_sync(0xffffffffu, s, o);
        if (lane == 0) logits[tt][e] = s;
    }
    __syncthreads();

    if (threadIdx.x < GT) {
        const int t = t0 + threadIdx.x;
        float sc[NE], sb[NE];
        #pragma unroll
        for (int e = 0; e < NE; e++) {
            float s = 1.f / (1.f + expf(-logits[threadIdx.x][e]));
            sc[e] = s; sb[e] = s + gb[e];
        }
        float gsc[NG];
        #pragma unroll
        for (int g = 0; g < NG; g++) {
            float m1 = -1e30f, m2 = -1e30f;
            #pragma unroll
            for (int j = 0; j < GSZ; j++) {
                float v = sb[g * GSZ + j];
                if (v > m1) { m2 = m1; m1 = v; } else if (v > m2) m2 = v;
            }
            gsc[g] = m1 + m2;
        }
        int g1 = 0; float b1 = gsc[0];
        for (int g = 1; g < NG; g++) if (gsc[g] > b1) { b1 = gsc[g]; g1 = g; }
        int g2 = -1; float b2 = -1e30f;
        for (int g = 0; g < NG; g++) if (g != g1 && gsc[g] > b2) { b2 = gsc[g]; g2 = g; }
        bool used[NE];
        #pragma unroll
        for (int e = 0; e < NE; e++) used[e] = !((e / GSZ) == g1 || (e / GSZ) == g2);
        float wtmp[TOPK]; float wsum = 0.f;
        #pragma unroll
        for (int k = 0; k < TOPK; k++) {
            int best = -1; float bv = -1e30f;
            for (int e = 0; e < NE; e++)
                if (!used[e] && sb[e] > bv) { bv = sb[e]; best = e; }
            used[best] = true;
            g_topi[t * TOPK + k] = best;
            atomicAdd(&g_counts[best], 1);
            wtmp[k] = sc[best]; wsum += sc[best];
        }
        float inv = RSCALE / wsum;
        #pragma unroll
        for (int k = 0; k < TOPK; k++) g_wsel[t * TOPK + k] = wtmp[k] * inv;
    }
}

__global__ void scan_kernel()
{
    if (threadIdx.x == 0) {
        int s = 0, nt = 0;
        for (int e = 0; e < NE; e++) {
            g_off[e] = s; g_cursor[e] = s;
            int c = g_counts[e];
            int tiles = (c + 127) >> 7;
            for (int j = 0; j < tiles; j++) { g_tile_e[nt] = e; g_tile_m0[nt] = s + j * 128; nt++; }
            s += tiles << 7;
        }
        g_ntiles = nt;
    }
}

__global__ void scatter_kernel()
{
    int i = blockIdx.x * blockDim.x + threadIdx.x;
    if (i < NROWS) {
        int e = g_topi[i];
        int pos = atomicAdd(&g_cursor[e], 1);
        g_gtok[pos] = i / TOPK;
        g_gw[pos]   = g_wsel[i];
        g_rowidx[i] = pos;
    }
}

// combine: ylat[t] = sum_k yg[rowidx[t,k]]; split into gcat cols 0-1023 (pitch NCAT)
__global__ void combine_kernel()
{
    int t = blockIdx.x;
    int l4 = threadIdx.x;
    int ridx[TOPK];
    #pragma unroll
    for (int k = 0; k < TOPK; k++) ridx[k] = g_rowidx[t * TOPK + k];
    float4 s = make_float4(0.f, 0.f, 0.f, 0.f);
    #pragma unroll
    for (int k = 0; k < TOPK; k++) {
        const float4 v = reinterpret_cast<const float4*>(gyg + (long)ridx[k] * LATD)[l4];
        s.x += v.x; s.y += v.y; s.z += v.z; s.w += v.w;
    }
    split_store4(s, gcat_hi, gcat_lo, (long)t * NCAT + l4 * 4);
}

// ---------------- HMMA GEMM-NT, 3-term bf16 split ----------------
// EPI: 0 fp32 store; 2 relu2*rscale -> split; 5 mixed; 6 red.global.add.f32
#define STAGE_BYTES 32768
#define GEMM_SMEM (3 * STAGE_BYTES)

template<int EPI, bool GROUPED, bool GATHER>
__global__ void __launch_bounds__(256, 2)
hgemm(const __nv_bfloat16* __restrict__ Ah_, const __nv_bfloat16* __restrict__ Al_,
      const __nv_bfloat16* __restrict__ Bh_, const __nv_bfloat16* __restrict__ Bl_,
      float* __restrict__ Cf,
      __nv_bfloat16* __restrict__ C1hi, __nv_bfloat16* __restrict__ C1lo,
      __nv_bfloat16* __restrict__ C2hi, __nv_bfloat16* __restrict__ C2lo,
      const float* __restrict__ rsc,
      int N, int K, int ldA, int ldB, int expertN, int col_off)
{
    extern __shared__ char smem[];
    int m0, brow0;
    if (GROUPED) {
        if ((int)blockIdx.y >= g_ntiles) return;
        m0    = g_tile_m0[blockIdx.y];
        brow0 = g_tile_e[blockIdx.y] * expertN + blockIdx.x * 128;
    } else {
        m0    = blockIdx.y * 128;
        brow0 = blockIdx.x * 128;
    }
    const int col0 = blockIdx.x * 128 + col_off;
    const int tid = threadIdx.x;
    const int wid = tid >> 5, lane = tid & 31;
    const uint32_t sb = smem_u32(smem);

    const int lrow = tid >> 2;
    const int lch  = tid & 3;
    const uint32_t so0 = (uint32_t)(lrow * 64 + ((lch ^ (lrow & 3)) << 4));
    const uint32_t so1 = so0 + 64 * 64;

    long ra0, ra1;
    if (GATHER) {
        ra0 = (long)g_gtok[m0 + lrow] * ldA;
        ra1 = (long)g_gtok[m0 + lrow + 64] * ldA;
    } else {
        ra0 = (long)(m0 + lrow) * ldA;
        ra1 = (long)(m0 + lrow + 64) * ldA;
    }
    const __nv_bfloat16* rowAh0 = Ah_ + ra0;
    const __nv_bfloat16* rowAh1 = Ah_ + ra1;
    const __nv_bfloat16* rowAl0 = Al_ + ra0;
    const __nv_bfloat16* rowAl1 = Al_ + ra1;
    const __nv_bfloat16* rowBh0 = Bh_ + (long)(brow0 + lrow) * ldB;
    const __nv_bfloat16* rowBh1 = rowBh0 + (long)64 * ldB;
    const __nv_bfloat16* rowBl0 = Bl_ + (long)(brow0 + lrow) * ldB;
    const __nv_bfloat16* rowBl1 = rowBl0 + (long)64 * ldB;

    const int wm = (wid & 3) * 32, wn = (wid >> 2) * 64;
    const int arow = wm + (lane & 15);
    const int brow = wn + (lane & 15);
    const int lhalf = lane >> 4;

    float acc[2][8][4];
    #pragma unroll
    for (int mi = 0; mi < 2; mi++)
        #pragma unroll
        for (int ni = 0; ni < 8; ni++)
            #pragma unroll
            for (int r = 0; r < 4; r++) acc[mi][ni][r] = 0.f;

    const int NT = K >> 5;

#define LOAD_STAGE(kt, s) do {                                                  \
    const long ko = (long)(kt) * 32 + lch * 8;                                  \
    uint32_t base = sb + (uint32_t)(s) * STAGE_BYTES;                           \
    cp16(base         + so0, rowAh0 + ko);                                      \
    cp16(base         + so1, rowAh1 + ko);                                      \
    cp16(base + 8192  + so0, rowAl0 + ko);                                      \
    cp16(base + 8192  + so1, rowAl1 + ko);                                      \
    cp16(base + 16384 + so0, rowBh0 + ko);                                      \
    cp16(base + 16384 + so1, rowBh1 + ko);                                      \
    cp16(base + 24576 + so0, rowBl0 + ko);                                      \
    cp16(base + 24576 + so1, rowBl1 + ko);                                      \
    asm volatile("cp.async.commit_group;" ::: "memory");                        \
} while (0)

    LOAD_STAGE(0, 0);
    LOAD_STAGE(1, 1);

    for (int kt = 0; kt < NT; kt++) {
        if (kt + 1 < NT) {
            asm volatile("cp.async.wait_group 1;" ::: "memory");
        } else {
            asm volatile("cp.async.wait_group 0;" ::: "memory");
        }
        __syncthreads();
        if (kt + 2 < NT) {
            LOAD_STAGE(kt + 2, (kt + 2) % 3);
        }

        const uint32_t sA = sb + (uint32_t)(kt % 3) * STAGE_BYTES;
        #pragma unroll
        for (int ks = 0; ks < 2; ks++) {
            const uint32_t axor = (uint32_t)((((ks * 2 + lhalf) ^ (arow & 3))) << 4);
            const uint32_t bxor = (uint32_t)((((ks * 2 + lhalf) ^ (brow & 3))) << 4);
            uint32_t ah[2][4], al[2][4];
            ldsm4(ah[0], sA + (uint32_t)(arow * 64) + axor);
            ldsm4(ah[1], sA + (uint32_t)((arow + 16) * 64) + axor);
            ldsm4(al[0], sA + 8192 + (uint32_t)(arow * 64) + axor);
            ldsm4(al[1], sA + 8192 + (uint32_t)((arow + 16) * 64) + axor);
            #pragma unroll
            for (int ng = 0; ng < 4; ng++) {
                uint32_t bh[4], bl[4];
                const uint32_t bo = (uint32_t)((brow + ng * 16) * 64);
                ldsm4(bh, sA + 16384 + bo + bxor);
                ldsm4(bl, sA + 24576 + bo + bxor);
                #pragma unroll
                for (int mi = 0; mi < 2; mi++) {
                    mma16816(acc[mi][ng * 2],     ah[mi], bh[0], bh[2]);
                    mma16816(acc[mi][ng * 2 + 1], ah[mi], bh[1], bh[3]);
                    mma16816(acc[mi][ng * 2],     ah[mi], bl[0], bl[2]);
                    mma16816(acc[mi][ng * 2 + 1], ah[mi], bl[1], bl[3]);
                    mma16816(acc[mi][ng * 2],     al[mi], bh[0], bh[2]);
                    mma16816(acc[mi][ng * 2 + 1], al[mi], bh[1], bh[3]);
                }
            }
        }
    }
#undef LOAD_STAGE

    const bool lowCols = (col0 < LATD);   // for EPI 5
    #pragma unroll
    for (int mi = 0; mi < 2; mi++) {
        #pragma unroll
        for (int ni = 0; ni < 8; ni++) {
            const float* d = acc[mi][ni];
            const int rr = m0 + wm + mi * 16 + (lane >> 2);
            const int cc = col0 + wn + ni * 8 + (lane & 3) * 2;
            #pragma unroll
            for (int half = 0; half < 2; half++) {
                const int r = rr + half * 8;
                float v0 = d[half * 2], v1 = d[half * 2 + 1];
                if (EPI == 0) {
                    *reinterpret_cast<float2*>(&Cf[(long)r * N + cc]) = make_float2(v0, v1);
                } else if (EPI == 6) {
                    redadd(&Cf[(long)r * N + cc], v0);
                    redadd(&Cf[(long)r * N + cc + 1], v1);
                } else if (EPI == 2) {
                    const float w = rsc[r];
                    float u0 = fmaxf(v0, 0.f); v0 = u0 * u0 * w;
                    float u1 = fmaxf(v1, 0.f); v1 = u1 * u1 * w;
                    __nv_bfloat16 h0, l0, h1, l1;
                    split_val(v0, h0, l0); split_val(v1, h1, l1);
                    *reinterpret_cast<__nv_bfloat162*>(&C1hi[(long)r * N + cc]) = __nv_bfloat162(h0, h1);
                    *reinterpret_cast<__nv_bfloat162*>(&C1lo[(long)r * N + cc]) = __nv_bfloat162(l0, l1);
                } else { // EPI == 5
                    if (lowCols) {
                        __nv_bfloat16 h0, l0, h1, l1;
                        split_val(v0, h0, l0); split_val(v1, h1, l1);
                        *reinterpret_cast<__nv_bfloat162*>(&C1hi[(long)r * LATD + cc]) = __nv_bfloat162(h0, h1);
                        *reinterpret_cast<__nv_bfloat162*>(&C1lo[(long)r * LATD + cc]) = __nv_bfloat162(l0, l1);
                    } else {
                        float u0 = fmaxf(v0, 0.f); v0 = u0 * u0;
                        float u1 = fmaxf(v1, 0.f); v1 = u1 * u1;
                        __nv_bfloat16 h0, l0, h1, l1;
                        split_val(v0, h0, l0); split_val(v1, h1, l1);
                        *reinterpret_cast<__nv_bfloat162*>(&C2hi[(long)r * NCAT + cc]) = __nv_bfloat162(h0, h1);
                        *reinterpret_cast<__nv_bfloat162*>(&C2lo[(long)r * NCAT + cc]) = __nv_bfloat162(l0, l1);
                    }
                }
            }
        }
    }
}

// ---------------- host ----------------
static void* sym(const void* s) { void* p; cudaGetSymbolAddress(&p, s); return p; }

extern "C" void kernel_launch(void* const* d_in, const int* in_sizes, int n_in,
                              void* d_out, int out_size)
{
    const float* x      = (const float*)d_in[0];
    const float* gate_w = (const float*)d_in[1];
    const float* gate_b = (const float*)d_in[2];
    const float* fc1_w  = (const float*)d_in[3];
    const float* fc2_w  = (const float*)d_in[4];
    const float* w1     = (const float*)d_in[5];
    const float* w2     = (const float*)d_in[6];
    const float* sup    = (const float*)d_in[7];
    const float* sdn    = (const float*)d_in[8];
    float* out = (float*)d_out;

    __nv_bfloat16* px_hi   = (__nv_bfloat16*)sym(gx_hi);   __nv_bfloat16* px_lo   = (__nv_bfloat16*)sym(gx_lo);
    __nv_bfloat16* pB1_hi  = (__nv_bfloat16*)sym(gB1_hi);  __nv_bfloat16* pB1_lo  = (__nv_bfloat16*)sym(gB1_lo);
    __nv_bfloat16* pw1_hi  = (__nv_bfloat16*)sym(gw1_hi);  __nv_bfloat16* pw1_lo  = (__nv_bfloat16*)sym(gw1_lo);
    __nv_bfloat16* pw2_hi  = (__nv_bfloat16*)sym(gw2_hi);  __nv_bfloat16* pw2_lo  = (__nv_bfloat16*)sym(gw2_lo);
    __nv_bfloat16* pwc_hi  = (__nv_bfloat16*)sym(gwcat_hi); __nv_bfloat16* pwc_lo = (__nv_bfloat16*)sym(gwcat_lo);
    __nv_bfloat16* pxlat_hi = (__nv_bfloat16*)sym(gxlat_hi); __nv_bfloat16* pxlat_lo = (__nv_bfloat16*)sym(gxlat_lo);
    __nv_bfloat16* ph_hi   = (__nv_bfloat16*)sym(gh_hi);   __nv_bfloat16* ph_lo   = (__nv_bfloat16*)sym(gh_lo);
    float*         pyg     = (float*)sym(gyg);
    __nv_bfloat16* pcat_hi = (__nv_bfloat16*)sym(gcat_hi); __nv_bfloat16* pcat_lo = (__nv_bfloat16*)sym(gcat_lo);
    float*         pgw     = (float*)sym(g_gw);

    cudaFuncSetAttribute((hgemm<6, false, false>), cudaFuncAttributeMaxDynamicSharedMemorySize, GEMM_SMEM);
    cudaFuncSetAttribute((hgemm<5, false, false>), cudaFuncAttributeMaxDynamicSharedMemorySize, GEMM_SMEM);
    cudaFuncSetAttribute((hgemm<2, true, true>),   cudaFuncAttributeMaxDynamicSharedMemorySize, GEMM_SMEM);
    cudaFuncSetAttribute((hgemm<0, true, false>),  cudaFuncAttributeMaxDynamicSharedMemorySize, GEMM_SMEM);

    // lazy one-time streams + events (host objects only; no device allocation)
    static bool s_init = false;
    static cudaStream_t s1, s2;
    static cudaEvent_t eFork, eSplitA, eSplitB, eRoute, e7a, eZero;
    if (!s_init) {
        cudaStreamCreateWithFlags(&s1, cudaStreamNonBlocking);
        cudaStreamCreateWithFlags(&s2, cudaStreamNonBlocking);
        cudaEventCreateWithFlags(&eFork,   cudaEventDisableTiming);
        cudaEventCreateWithFlags(&eSplitA, cudaEventDisableTiming);
        cudaEventCreateWithFlags(&eSplitB, cudaEventDisableTiming);
        cudaEventCreateWithFlags(&eRoute,  cudaEventDisableTiming);
        cudaEventCreateWithFlags(&e7a,     cudaEventDisableTiming);
        cudaEventCreateWithFlags(&eZero,   cudaEventDisableTiming);
        s_init = true;
    }

    // ---- fork side streams (R15 structure; zero_out moved to s2) ----
    cudaEventRecord(eFork, 0);
    cudaStreamWaitEvent(s1, eFork, 0);
    cudaStreamWaitEvent(s2, eFork, 0);

    // s2: zero out (16 MB stores) -- overlaps split_A, no chain behind it
    zero_out_kernel<<<T_TOK * H_DIM / 4 / 256, 256, 0, s2>>>((float4*)out);
    cudaEventRecord(eZero, s2);

    // main: splits start immediately
    split_a_kernel<<<SPLITA_BLOCKS, 256>>>((const float4*)x, (const float4*)fc1_w,
                                           (const float4*)sup);
    cudaEventRecord(eSplitA, 0);

    split_b_kernel<<<SPLITB_BLOCKS, 256>>>((const float4*)w1, (const float4*)w2,
                                           (const float4*)fc2_w, (const float4*)sdn);
    cudaEventRecord(eSplitB, 0);

    // s1: routing chain (raw x only; overlaps splits), then 3b, then G7a
    zero_counts_kernel<<<1, 32, 0, s1>>>();
    gate_kernel<<<T_TOK / GT, 256, 0, s1>>>(x, gate_w, gate_b);
    scan_kernel<<<1, 32, 0, s1>>>();
    scatter_kernel<<<(NROWS + 255) / 256, 256, 0, s1>>>();
    cudaEventRecord(eRoute, s1);
    // s1: 3b needs phase-A split only
    cudaStreamWaitEvent(s1, eSplitA, 0);
    hgemm<5, false, false><<<dim3(SH_INTER / 128, T_TOK / 128), 256, GEMM_SMEM, s1>>>(
        px_hi, px_lo, pB1_hi + (long)LATD * H_DIM, pB1_lo + (long)LATD * H_DIM, nullptr,
        nullptr, nullptr, pcat_hi, pcat_lo, nullptr,
        NCAT, H_DIM, H_DIM, H_DIM, 0, LATD);
    // s1: G7a (RED-add) needs 3b output + wcat + zeroed out
    cudaStreamWaitEvent(s1, eSplitB, 0);
    cudaStreamWaitEvent(s1, eZero, 0);
    hgemm<6, false, false><<<dim3(H_DIM / 128, T_TOK / 128), 256, GEMM_SMEM, s1>>>(
        pcat_hi + LATD, pcat_lo + LATD, pwc_hi + LATD, pwc_lo + LATD, out,
        nullptr, nullptr, nullptr, nullptr, nullptr,
        H_DIM, SH_INTER, NCAT, NCAT, 0, 0);
    cudaEventRecord(e7a, s1);

    // main: 3a = x @ fc1^T -> xlat split
    hgemm<5, false, false><<<dim3(LATD / 128, T_TOK / 128), 256, GEMM_SMEM>>>(
        px_hi, px_lo, pB1_hi, pB1_lo, nullptr,
        pxlat_hi, pxlat_lo, nullptr, nullptr, nullptr,
        NCAT, H_DIM, H_DIM, H_DIM, 0, 0);

    // G4 needs routing + w1
    cudaStreamWaitEvent(0, eRoute, 0);
    hgemm<2, true, true><<<dim3(INTERD / 128, GTILES), 256, GEMM_SMEM>>>(
        pxlat_hi, pxlat_lo, pw1_hi, pw1_lo, nullptr,
        ph_hi, ph_lo, nullptr, nullptr, pgw,
        INTERD, LATD, LATD, LATD, INTERD, 0);

    // G5: yg = h @ w2[e]^T (fp32)
    hgemm<0, true, false><<<dim3(LATD / 128, GTILES), 256, GEMM_SMEM>>>(
        ph_hi, ph_lo, pw2_hi, pw2_lo, pyg,
        nullptr, nullptr, nullptr, nullptr, nullptr,
        LATD, INTERD, INTERD, INTERD, LATD, 0);

    // combine -> gcat cols 0-1023
    combine_kernel<<<T_TOK, 256>>>();

    // main: G7b (RED-add) needs zeroed out (wait is long satisfied by now)
    cudaStreamWaitEvent(0, eZero, 0);
    hgemm<6, false, false><<<dim3(H_DIM / 128, T_TOK / 128), 256, GEMM_SMEM>>>(
        pcat_hi, pcat_lo, pwc_hi, pwc_lo, out,
        nullptr, nullptr, nullptr, nullptr, nullptr,
        H_DIM, LATD, NCAT, NCAT, 0, 0);

    // join s1 into origin stream for graph-capture completeness (after G7b)
    cudaStreamWaitEvent(0, e7a, 0);
}